// round 12
// baseline (speedup 1.0000x reference)
#include <cuda_runtime.h>
#include <cuda_bf16.h>
#include <math.h>
#include <stdint.h>

// Problem constants
#define Bq   4
#define Lq   2048
#define DMq  256
#define Hq   8
#define Eq   32
#define NLq  3
#define INTERq 16
#define Uq   40
#define BLq  (Bq*Lq)     // 8192
#define QB   8           // queries per attn block (40 = 5 groups * 8)
#define GRPS 5

// ---------------- scratch (device globals; no allocation allowed) -------------
__device__ float g_x[BLq*DMq];
__device__ float g_q[BLq*DMq];
__device__ float g_k[BLq*DMq];
__device__ float g_v[BLq*DMq];
__device__ float g_tmp[BLq*DMq];
__device__ __nv_bfloat16 g_ahi[BLq*DMq];
__device__ __nv_bfloat16 g_alo[BLq*DMq];
__device__ __nv_bfloat16 g_whi[12*DMq*DMq];   // [lay*4+slot][n][k]
__device__ __nv_bfloat16 g_wlo[12*DMq*DMq];
__device__ __nv_bfloat16 g_cwhi[6*DMq*DMq];   // [lay*3+t][o][i]
__device__ __nv_bfloat16 g_cwlo[6*DMq*DMq];
__device__ float g_wot[DMq*DMq];              // WO^T for current layer
__device__ float g_ybase[Bq*DMq];             // vmean @ WO^T + bo
__device__ int   g_selmap[Bq*Hq*Lq];          // tag<<12 | u, tag = lay+1
__device__ int   g_idx[NLq*Lq*Uq];
__device__ float g_M[Bq*Hq*Lq];
__device__ int   g_top[Bq*Hq*Uq];
__device__ float g_vmean[Bq*DMq];
__device__ float g_vpart[Bq*32*DMq];
__device__ float g_upd[Bq*Hq*Uq*Eq];
__device__ float g_bnp1[256*DMq];
__device__ float g_bnp2[256*DMq];
__device__ float g_bnm[DMq];
__device__ float g_bnv[DMq];

// ---------------- Threefry-2x32 (matches JAX) ---------------------------------
__host__ __device__ inline void tf2x32(uint32_t k0, uint32_t k1,
                                       uint32_t x0, uint32_t x1,
                                       uint32_t& o0, uint32_t& o1) {
    uint32_t ks[3];
    ks[0] = k0; ks[1] = k1; ks[2] = k0 ^ k1 ^ 0x1BD11BDAu;
    x0 += ks[0]; x1 += ks[1];
    const int R0[4] = {13, 15, 26, 6};
    const int R1[4] = {17, 29, 16, 24};
    #pragma unroll
    for (int i = 0; i < 5; i++) {
        #pragma unroll
        for (int j = 0; j < 4; j++) {
            int r = (i & 1) ? R1[j] : R0[j];
            x0 += x1;
            x1 = (x1 << r) | (x1 >> (32 - r));
            x1 ^= x0;
        }
        x0 += ks[(i + 1) % 3];
        x1 += ks[(i + 2) % 3] + (uint32_t)(i + 1);
    }
    o0 = x0; o1 = x1;
}

// all-layer RNG: idx[lay][f] = lower_bits(tf(split(fold_in(key42,lay))[1],(0,f))) & 2047
__global__ void rng_idx_all_kernel() {
    int t = blockIdx.x * blockDim.x + threadIdx.x;
    if (t < NLq * Lq * Uq) {
        int lay = t / (Lq * Uq);
        int f = t - lay * (Lq * Uq);
        uint32_t k0, k1, s0, s1, o0, o1;
        tf2x32(0u, 42u, 0u, (uint32_t)lay, k0, k1);
        tf2x32(k0, k1, 0u, 1u, s0, s1);
        tf2x32(s0, s1, 0u, (uint32_t)f, o0, o1);
        g_idx[t] = (int)((o0 ^ o1) & 2047u);
    }
}

// ---------------- block-sum helper (256 threads) -------------------------------
__device__ __forceinline__ float bsum256(float v, float* s8, int lane, int wid) {
    #pragma unroll
    for (int o = 16; o > 0; o >>= 1) v += __shfl_xor_sync(0xffffffffu, v, o);
    if (lane == 0) s8[wid] = v;
    __syncthreads();
    float r = s8[0] + s8[1] + s8[2] + s8[3] + s8[4] + s8[5] + s8[6] + s8[7];
    __syncthreads();
    return r;
}

// ---------------- copy input x + bf16 split ------------------------------------
__global__ void copy_x_kernel(const float* __restrict__ src) {
    int t = blockIdx.x * blockDim.x + threadIdx.x;
    if (t < BLq * DMq) {
        float v = src[t];
        g_x[t] = v;
        __nv_bfloat16 h = __float2bfloat16(v);
        g_ahi[t] = h;
        g_alo[t] = __float2bfloat16(v - __bfloat162float(h));
    }
}

__global__ void split_w_kernel(const float* __restrict__ src, int slot) {
    int t = blockIdx.x * blockDim.x + threadIdx.x;
    if (t < NLq * DMq * DMq) {
        int lay = t >> 16;
        int r = t & 65535;
        float v = src[t];
        __nv_bfloat16 h = __float2bfloat16(v);
        int d = (((lay << 2) + slot) << 16) | r;
        g_whi[d] = h;
        g_wlo[d] = __float2bfloat16(v - __bfloat162float(h));
    }
}

__global__ void split_cw_kernel(const float* __restrict__ dcw) {
    int t = blockIdx.x * blockDim.x + threadIdx.x;
    if (t < (NLq - 1) * 3 * DMq * DMq) {
        int lay = t / (3 * 65536);
        int rem = t % (3 * 65536);
        int tap = rem >> 16;
        int oi = rem & 65535;
        int o = oi >> 8;
        int i = oi & 255;
        float v = dcw[(size_t)lay * 3 * 65536 + o * 768 + i * 3 + tap];
        __nv_bfloat16 h = __float2bfloat16(v);
        g_cwhi[t] = h;
        g_cwlo[t] = __float2bfloat16(v - __bfloat162float(h));
    }
}

// ---------------- split-bf16 tensor-core GEMM ----------------------------------
#define MMA_BF16(c, a, b) \
    asm volatile("mma.sync.aligned.m16n8k16.row.col.f32.bf16.bf16.f32 " \
        "{%0,%1,%2,%3}, {%4,%5,%6,%7}, {%8,%9}, {%0,%1,%2,%3};" \
        : "+f"((c)[0]), "+f"((c)[1]), "+f"((c)[2]), "+f"((c)[3]) \
        : "r"((a)[0]), "r"((a)[1]), "r"((a)[2]), "r"((a)[3]), \
          "r"((b)[0]), "r"((b)[1]))

// fused QKV: grid (2, 64, 3), 256 threads
__global__ __launch_bounds__(256)
void gemm_qkv_kernel(int lay,
                     const float* __restrict__ bq,
                     const float* __restrict__ bk,
                     const float* __restrict__ bv,
                     float* __restrict__ Cq,
                     float* __restrict__ Ck,
                     float* __restrict__ Cv) {
    __shared__ __nv_bfloat16 sAh[2][128*24], sAl[2][128*24];
    __shared__ __nv_bfloat16 sBh[2][128*24], sBl[2][128*24];
    int z = blockIdx.z;
    int slot = lay * 4 + z;
    const float* bias = (z == 0) ? bq : (z == 1) ? bk : bv;
    float* C = (z == 0) ? Cq : (z == 1) ? Ck : Cv;

    int tid = threadIdx.x;
    int m0 = blockIdx.y * 128, n0 = blockIdx.x * 128;
    int lr = tid >> 1, lh = tid & 1;
    int w = tid >> 5, lane = tid & 31;
    int wm = w & 1, wn = w >> 1;
    int grp = lane >> 2, tig = lane & 3;

    const __nv_bfloat16* Wh = g_whi + (size_t)slot * DMq * DMq;
    const __nv_bfloat16* Wl = g_wlo + (size_t)slot * DMq * DMq;
    size_t aoff = (size_t)(m0 + lr) * DMq + lh * 8;
    size_t boff = (size_t)(n0 + lr) * DMq + lh * 8;
    int sidx = lr * 24 + lh * 8;

    float acc[4][4][4];
    #pragma unroll
    for (int i = 0; i < 4; i++)
        #pragma unroll
        for (int j = 0; j < 4; j++)
            #pragma unroll
            for (int q = 0; q < 4; q++) acc[i][j][q] = 0.f;

    uint4 rah = *(const uint4*)(g_ahi + aoff);
    uint4 ral = *(const uint4*)(g_alo + aoff);
    uint4 rbh = *(const uint4*)(Wh + boff);
    uint4 rbl = *(const uint4*)(Wl + boff);

    for (int c = 0; c < 16; c++) {
        int p = c & 1;
        *(uint4*)(sAh[p] + sidx) = rah;
        *(uint4*)(sAl[p] + sidx) = ral;
        *(uint4*)(sBh[p] + sidx) = rbh;
        *(uint4*)(sBl[p] + sidx) = rbl;
        __syncthreads();
        if (c + 1 < 16) {
            rah = *(const uint4*)(g_ahi + aoff + (c + 1) * 16);
            ral = *(const uint4*)(g_alo + aoff + (c + 1) * 16);
            rbh = *(const uint4*)(Wh + boff + (c + 1) * 16);
            rbl = *(const uint4*)(Wl + boff + (c + 1) * 16);
        }
        uint32_t bh[4][2], bl[4][2];
        #pragma unroll
        for (int nf = 0; nf < 4; nf++) {
            int n = wn * 32 + nf * 8 + grp;
            bh[nf][0] = *(const uint32_t*)(sBh[p] + n * 24 + tig * 2);
            bh[nf][1] = *(const uint32_t*)(sBh[p] + n * 24 + tig * 2 + 8);
            bl[nf][0] = *(const uint32_t*)(sBl[p] + n * 24 + tig * 2);
            bl[nf][1] = *(const uint32_t*)(sBl[p] + n * 24 + tig * 2 + 8);
        }
        #pragma unroll
        for (int mf = 0; mf < 4; mf++) {
            int r = wm * 64 + mf * 16 + grp;
            uint32_t ah[4], al[4];
            ah[0] = *(const uint32_t*)(sAh[p] + r * 24 + tig * 2);
            ah[1] = *(const uint32_t*)(sAh[p] + (r + 8) * 24 + tig * 2);
            ah[2] = *(const uint32_t*)(sAh[p] + r * 24 + tig * 2 + 8);
            ah[3] = *(const uint32_t*)(sAh[p] + (r + 8) * 24 + tig * 2 + 8);
            al[0] = *(const uint32_t*)(sAl[p] + r * 24 + tig * 2);
            al[1] = *(const uint32_t*)(sAl[p] + (r + 8) * 24 + tig * 2);
            al[2] = *(const uint32_t*)(sAl[p] + r * 24 + tig * 2 + 8);
            al[3] = *(const uint32_t*)(sAl[p] + (r + 8) * 24 + tig * 2 + 8);
            #pragma unroll
            for (int nf = 0; nf < 4; nf++) {
                MMA_BF16(acc[mf][nf], ah, bh[nf]);
                MMA_BF16(acc[mf][nf], ah, bl[nf]);
                MMA_BF16(acc[mf][nf], al, bh[nf]);
            }
        }
    }

    #pragma unroll
    for (int mf = 0; mf < 4; mf++) {
        int r0 = m0 + wm * 64 + mf * 16 + grp;
        #pragma unroll
        for (int nf = 0; nf < 4; nf++) {
            int c0 = n0 + wn * 32 + nf * 8 + tig * 2;
            float2 v0 = {acc[mf][nf][0] + bias[c0], acc[mf][nf][1] + bias[c0 + 1]};
            float2 v1 = {acc[mf][nf][2] + bias[c0], acc[mf][nf][3] + bias[c0 + 1]};
            *(float2*)&C[(size_t)r0 * DMq + c0] = v0;
            *(float2*)&C[(size_t)(r0 + 8) * DMq + c0] = v1;
        }
    }
}

// ---------------- conv as 3-tap split-bf16 GEMM --------------------------------
__global__ __launch_bounds__(256)
void convgemm_bf16_kernel(int lay, const float* __restrict__ cb) {
    __shared__ __nv_bfloat16 sAh[2][128*24], sAl[2][128*24];
    __shared__ __nv_bfloat16 sBh[2][128*24], sBl[2][128*24];
    int tid = threadIdx.x;
    int m0 = blockIdx.y * 128, n0 = blockIdx.x * 128;
    int lr = tid >> 1, lh = tid & 1;
    int w = tid >> 5, lane = tid & 31;
    int wm = w & 1, wn = w >> 1;
    int grp = lane >> 2, tig = lane & 3;

    int m = m0 + lr;
    int b = m >> 11;
    int l = m & 2047;
    size_t aoff[3];
    #pragma unroll
    for (int t = 0; t < 3; t++)
        aoff[t] = (size_t)((b << 11) | ((l + t + 2047) & 2047)) * DMq + lh * 8;
    const __nv_bfloat16* Wh3 = g_cwhi + (size_t)(lay * 3) * DMq * DMq;
    const __nv_bfloat16* Wl3 = g_cwlo + (size_t)(lay * 3) * DMq * DMq;
    size_t boff = (size_t)(n0 + lr) * DMq + lh * 8;
    int sidx = lr * 24 + lh * 8;

    float acc[4][4][4];
    #pragma unroll
    for (int i = 0; i < 4; i++)
        #pragma unroll
        for (int j = 0; j < 4; j++)
            #pragma unroll
            for (int q = 0; q < 4; q++) acc[i][j][q] = 0.f;

    uint4 rah = *(const uint4*)(g_ahi + aoff[0]);
    uint4 ral = *(const uint4*)(g_alo + aoff[0]);
    uint4 rbh = *(const uint4*)(Wh3 + boff);
    uint4 rbl = *(const uint4*)(Wl3 + boff);

    for (int kt = 0; kt < 48; kt++) {
        int p = kt & 1;
        *(uint4*)(sAh[p] + sidx) = rah;
        *(uint4*)(sAl[p] + sidx) = ral;
        *(uint4*)(sBh[p] + sidx) = rbh;
        *(uint4*)(sBl[p] + sidx) = rbl;
        __syncthreads();
        if (kt + 1 < 48) {
            int t2 = (kt + 1) >> 4;
            int c2 = ((kt + 1) & 15) * 16;
            rah = *(const uint4*)(g_ahi + aoff[t2] + c2);
            ral = *(const uint4*)(g_alo + aoff[t2] + c2);
            rbh = *(const uint4*)(Wh3 + (size_t)t2 * DMq * DMq + boff + c2);
            rbl = *(const uint4*)(Wl3 + (size_t)t2 * DMq * DMq + boff + c2);
        }
        uint32_t bh[4][2], bl[4][2];
        #pragma unroll
        for (int nf = 0; nf < 4; nf++) {
            int n = wn * 32 + nf * 8 + grp;
            bh[nf][0] = *(const uint32_t*)(sBh[p] + n * 24 + tig * 2);
            bh[nf][1] = *(const uint32_t*)(sBh[p] + n * 24 + tig * 2 + 8);
            bl[nf][0] = *(const uint32_t*)(sBl[p] + n * 24 + tig * 2);
            bl[nf][1] = *(const uint32_t*)(sBl[p] + n * 24 + tig * 2 + 8);
        }
        #pragma unroll
        for (int mf = 0; mf < 4; mf++) {
            int r = wm * 64 + mf * 16 + grp;
            uint32_t ah[4], al[4];
            ah[0] = *(const uint32_t*)(sAh[p] + r * 24 + tig * 2);
            ah[1] = *(const uint32_t*)(sAh[p] + (r + 8) * 24 + tig * 2);
            ah[2] = *(const uint32_t*)(sAh[p] + r * 24 + tig * 2 + 8);
            ah[3] = *(const uint32_t*)(sAh[p] + (r + 8) * 24 + tig * 2 + 8);
            al[0] = *(const uint32_t*)(sAl[p] + r * 24 + tig * 2);
            al[1] = *(const uint32_t*)(sAl[p] + (r + 8) * 24 + tig * 2);
            al[2] = *(const uint32_t*)(sAl[p] + r * 24 + tig * 2 + 8);
            al[3] = *(const uint32_t*)(sAl[p] + (r + 8) * 24 + tig * 2 + 8);
            #pragma unroll
            for (int nf = 0; nf < 4; nf++) {
                MMA_BF16(acc[mf][nf], ah, bh[nf]);
                MMA_BF16(acc[mf][nf], ah, bl[nf]);
                MMA_BF16(acc[mf][nf], al, bh[nf]);
            }
        }
    }

    #pragma unroll
    for (int mf = 0; mf < 4; mf++) {
        int r0 = m0 + wm * 64 + mf * 16 + grp;
        #pragma unroll
        for (int nf = 0; nf < 4; nf++) {
            int c0 = n0 + wn * 32 + nf * 8 + tig * 2;
            float2 v0 = {acc[mf][nf][0] + cb[c0], acc[mf][nf][1] + cb[c0 + 1]};
            float2 v1 = {acc[mf][nf][2] + cb[c0], acc[mf][nf][3] + cb[c0 + 1]};
            *(float2*)&g_tmp[(size_t)r0 * DMq + c0] = v0;
            *(float2*)&g_tmp[(size_t)(r0 + 8) * DMq + c0] = v1;
        }
    }
}

// ---------------- M: 4 threads per query ---------------------------------------
__global__ void compute_M_kernel(int lay) {
    int t = blockIdx.x * blockDim.x + threadIdx.x;
    int q = t >> 2;
    int j = t & 3;
    int l = q & (Lq - 1);
    int bh = q >> 11;
    int h = bh & (Hq - 1);
    int b = bh >> 3;
    const int* idx = g_idx + lay * (Lq * Uq);
    const float4* qp = (const float4*)(g_q + ((size_t)(b * Lq + l) * DMq + h * Eq + j * 8));
    float4 q0 = qp[0], q1 = qp[1];
    float mx = -INFINITY, sm = 0.f;
    #pragma unroll 4
    for (int s = 0; s < Uq; s++) {
        int kl = idx[l * Uq + s];
        const float4* kp = (const float4*)(g_k + ((size_t)(b * Lq + kl) * DMq + h * Eq + j * 8));
        float4 k0 = kp[0], k1 = kp[1];
        float d = q0.x*k0.x + q0.y*k0.y + q0.z*k0.z + q0.w*k0.w
                + q1.x*k1.x + q1.y*k1.y + q1.z*k1.z + q1.w*k1.w;
        d += __shfl_xor_sync(0xffffffffu, d, 1);
        d += __shfl_xor_sync(0xffffffffu, d, 2);
        mx = fmaxf(mx, d);
        sm += d;
    }
    if (j == 0) g_M[q] = mx - sm * (1.0f / (float)Lq);
}

// ---------------- top-k via full bitonic sort ----------------------------------
__device__ inline uint32_t fsortable(float f) {
    uint32_t u = __float_as_uint(f);
    return (u & 0x80000000u) ? ~u : (u | 0x80000000u);
}

__global__ __launch_bounds__(512)
void topk_kernel() {
    __shared__ unsigned long long key[Lq];
    int bh = blockIdx.x;
    int tid = threadIdx.x;
    const float* Mrow = g_M + (size_t)bh * Lq;
    for (int i = tid; i < Lq; i += 512) {
        uint32_t s = fsortable(Mrow[i]);
        key[i] = ((unsigned long long)(~s) << 32) | (uint32_t)i;
    }
    for (int k = 2; k <= Lq; k <<= 1) {
        for (int j = k >> 1; j > 0; j >>= 1) {
            __syncthreads();
            for (int i = tid; i < Lq; i += 512) {
                int l = i ^ j;
                if (l > i) {
                    unsigned long long a = key[i], c = key[l];
                    bool asc = ((i & k) == 0);
                    if ((a > c) == asc) { key[i] = c; key[l] = a; }
                }
            }
        }
    }
    __syncthreads();
    if (tid < Uq) g_top[bh * Uq + tid] = (int)(key[tid] & 0xffffffffu);
}

// ---------------- mean of v over L: two-stage ----------------------------------
__global__ void vmean_part_kernel() {
    int b = blockIdx.y;
    int chunk = blockIdx.x;
    int d = threadIdx.x;
    float s = 0.f;
    int r0 = chunk * 64;
    for (int r = 0; r < 64; r++)
        s += g_v[(size_t)(b * Lq + r0 + r) * DMq + d];
    g_vpart[(size_t)(b * 32 + chunk) * DMq + d] = s;
}

__global__ void vmean_final_kernel() {
    int b = blockIdx.x;
    int d = threadIdx.x;
    float s = 0.f;
    for (int c = 0; c < 32; c++) s += g_vpart[(size_t)(b * 32 + c) * DMq + d];
    g_vmean[b * DMq + d] = s * (1.0f / (float)Lq);
}

// ---------------- attention: QB=8 queries per block, 5 groups ------------------
__global__ __launch_bounds__(256)
void attn_kernel() {
    __shared__ float sp[QB][Lq];           // 64KB
    __shared__ float qs[QB][Eq];
    __shared__ float redm[QB][8];
    __shared__ float reds[QB][8];
    __shared__ float outacc[8][QB][Eq];    // 8KB
    const float SCALE = 0.17677669529663687f;
    int blk = blockIdx.x;
    int grp = blk % GRPS;
    int bh = blk / GRPS;
    int h = bh & (Hq - 1);
    int b = bh >> 3;
    int tid = threadIdx.x;
    int lane = tid & 31;
    int wid = tid >> 5;

    for (int i = tid; i < QB * Eq; i += 256) {
        int qq = i >> 5, e = i & 31;
        int lqi = g_top[bh * Uq + grp * QB + qq];
        qs[qq][e] = g_q[(size_t)(b * Lq + lqi) * DMq + h * Eq + e];
    }
    __syncthreads();

    float lmax[QB];
    #pragma unroll
    for (int qq = 0; qq < QB; qq++) lmax[qq] = -INFINITY;
    for (int kk = tid; kk < Lq; kk += 256) {
        const float4* k4 = (const float4*)(g_k + ((size_t)(b * Lq + kk) * DMq + h * Eq));
        float4 kv[8];
        #pragma unroll
        for (int j = 0; j < 8; j++) kv[j] = k4[j];
        #pragma unroll
        for (int qq = 0; qq < QB; qq++) {
            const float4* q4 = (const float4*)qs[qq];
            float d = 0.f;
            #pragma unroll
            for (int j = 0; j < 8; j++) {
                float4 qv = q4[j];
                d += qv.x*kv[j].x + qv.y*kv[j].y + qv.z*kv[j].z + qv.w*kv[j].w;
            }
            d *= SCALE;
            sp[qq][kk] = d;
            lmax[qq] = fmaxf(lmax[qq], d);
        }
    }
    #pragma unroll
    for (int qq = 0; qq < QB; qq++) {
        float v = lmax[qq];
        #pragma unroll
        for (int off = 16; off > 0; off >>= 1)
            v = fmaxf(v, __shfl_xor_sync(0xffffffffu, v, off));
        if (lane == 0) redm[qq][wid] = v;
    }
    __syncthreads();
    float gmax[QB];
    #pragma unroll
    for (int qq = 0; qq < QB; qq++) {
        float v = redm[qq][0];
        #pragma unroll
        for (int w2 = 1; w2 < 8; w2++) v = fmaxf(v, redm[qq][w2]);
        gmax[qq] = v;
    }

    float lsum[QB];
    #pragma unroll
    for (int qq = 0; qq < QB; qq++) lsum[qq] = 0.f;
    for (int kk = tid; kk < Lq; kk += 256) {
        #pragma unroll
        for (int qq = 0; qq < QB; qq++) {
            float p = expf(sp[qq][kk] - gmax[qq]);
            sp[qq][kk] = p;
            lsum[qq] += p;
        }
    }
    #pragma unroll
    for (int qq = 0; qq < QB; qq++) {
        float v = lsum[qq];
        #pragma unroll
        for (int off = 16; off > 0; off >>= 1)
            v += __shfl_xor_sync(0xffffffffu, v, off);
        if (lane == 0) reds[qq][wid] = v;
    }
    __syncthreads();
    float ginv[QB];
    #pragma unroll
    for (int qq = 0; qq < QB; qq++) {
        float v = 0.f;
        #pragma unroll
        for (int w2 = 0; w2 < 8; w2++) v += reds[qq][w2];
        ginv[qq] = 1.0f / v;
    }

    {
        int e = lane;
        float acc[QB];
        #pragma unroll
        for (int qq = 0; qq < QB; qq++) acc[qq] = 0.f;
        for (int kk = wid; kk < Lq; kk += 8) {
            float vv = g_v[(size_t)(b * Lq + kk) * DMq + h * Eq + e];
            #pragma unroll
            for (int qq = 0; qq < QB; qq++)
                acc[qq] += sp[qq][kk] * vv;
        }
        #pragma unroll
        for (int qq = 0; qq < QB; qq++) outacc[wid][qq][e] = acc[qq];
    }
    __syncthreads();
    if (tid < QB * Eq) {
        int qq = tid >> 5, e = tid & 31;
        float s = 0.f;
        #pragma unroll
        for (int w2 = 0; w2 < 8; w2++) s += outacc[w2][qq][e];
        g_upd[((size_t)bh * Uq + grp * QB + qq) * Eq + e] = s * ginv[qq];
    }
}

// ---------------- WO prep: wot transpose + ybase + selmap set ------------------
__global__ __launch_bounds__(256)
void wo_prep_kernel(int lay, const float* __restrict__ WO,
                    const float* __restrict__ bo) {
    int bid = blockIdx.x;
    int tid = threadIdx.x;
    if (bid < 256) {
        int t = bid * 256 + tid;           // t = d*256+n
        int d = t >> 8, n = t & 255;
        g_wot[t] = WO[n * DMq + d];
    } else if (bid < 288) {
        __shared__ float vm[DMq];
        int q = bid - 256;
        int b = q >> 3, ng = q & 7;
        vm[tid] = g_vmean[b * DMq + tid];
        __syncthreads();
        int nl = tid >> 3, dc = tid & 7;
        int n = ng * 32 + nl;
        const float4* w4 = (const float4*)(WO + (size_t)n * DMq + dc * 32);
        float s = 0.f;
        #pragma unroll
        for (int i = 0; i < 8; i++) {
            float4 wv = w4[i];
            int d0 = dc * 32 + i * 4;
            s += vm[d0]*wv.x + vm[d0+1]*wv.y + vm[d0+2]*wv.z + vm[d0+3]*wv.w;
        }
        s += __shfl_down_sync(0xffffffffu, s, 4);
        s += __shfl_down_sync(0xffffffffu, s, 2);
        s += __shfl_down_sync(0xffffffffu, s, 1);
        if (dc == 0) g_ybase[b * DMq + n] = s + bo[n];
    } else {
        int t = (bid - 288) * 256 + tid;   // B*H*U = 1280
        if (t < Bq * Hq * Uq) {
            int u = t % Uq;
            int bh = t / Uq;
            int l = g_top[t];
            g_selmap[bh * Lq + l] = ((lay + 1) << 12) | u;
        }
    }
}

// ---------------- fused: WO-apply -> LN1 -> FFN -> +res -> LN2 -> split --------
__global__ __launch_bounds__(256)
void post_kernel(int lay,
                 const float* __restrict__ c1w,
                 const float* __restrict__ c1b,
                 const float* __restrict__ c2w,
                 const float* __restrict__ c2b,
                 const float* __restrict__ g1,
                 const float* __restrict__ b1,
                 const float* __restrict__ g2,
                 const float* __restrict__ b2) {
    __shared__ float s8[8];
    __shared__ float xs[DMq];
    __shared__ float ys[INTERq];
    __shared__ int su[8];
    __shared__ float sdelta[8][Eq];
    int row = blockIdx.x;            // b*2048 + l
    int b = row >> 11;
    int l = row & 2047;
    int d = threadIdx.x;
    int lane = d & 31, wid = d >> 5;
    size_t off = (size_t)row * DMq + d;

    // --- inline wo_apply: acc = attention-output row @ WO^T + bo ---
    int tag = (lay + 1) << 12;
    if (d < 8) {
        int vv = g_selmap[(b * 8 + d) * Lq + l];
        su[d] = ((vv & ~4095) == tag) ? (vv & 4095) : -1;
    }
    __syncthreads();
    bool any = su[0] >= 0 || su[1] >= 0 || su[2] >= 0 || su[3] >= 0 ||
               su[4] >= 0 || su[5] >= 0 || su[6] >= 0 || su[7] >= 0;
    float acc = g_ybase[b * DMq + d];
    if (any) {
        int h = d >> 5, e = d & 31;
        int u = su[h];
        sdelta[h][e] = (u >= 0)
            ? g_upd[(((size_t)(b * 8 + h)) * Uq + u) * Eq + e] - g_vmean[b * DMq + h * 32 + e]
            : 0.f;
        __syncthreads();
        #pragma unroll
        for (int h2 = 0; h2 < 8; h2++) {
            if (su[h2] >= 0) {
                #pragma unroll
                for (int e2 = 0; e2 < 32; e2++)
                    acc += sdelta[h2][e2] * g_wot[(h2 * 32 + e2) * DMq + d];
            }
        }
    }

    // --- LN1(x + acc) ---
    float v = g_x[off] + acc;
    float m = bsum256(v, s8, lane, wid) * (1.0f / (float)DMq);
    float c = v - m;
    float var = bsum256(c * c, s8, lane, wid) * (1.0f / (float)DMq);
    float x1 = c * rsqrtf(var + 1e-5f) * g1[d] + b1[d];
    xs[d] = x1;
    __syncthreads();
    int f = d >> 4, kc = d & 15;
    const float4* w4 = (const float4*)(c1w + (size_t)f * DMq + kc * 16);
    float p = 0.f;
    #pragma unroll
    for (int i = 0; i < 4; i++) {
        float4 wv = w4[i];
        int k0 = kc * 16 + i * 4;
        p += xs[k0]*wv.x + xs[k0+1]*wv.y + xs[k0+2]*wv.z + xs[k0+3]*wv.w;
    }
    p += __shfl_down_sync(0xffffffffu, p, 8);
    p += __shfl_down_sync(0xffffffffu, p, 4);
    p += __shfl_down_sync(0xffffffffu, p, 2);
    p += __shfl_down_sync(0xffffffffu, p, 1);
    if (kc == 0) ys[f] = fmaxf(p + c1b[f], 0.f);
    __syncthreads();
    float a2 = c2b[d];
    const float* w2 = c2w + (size_t)d * INTERq;
    #pragma unroll
    for (int ff = 0; ff < INTERq; ff++) a2 += ys[ff] * w2[ff];
    float v2 = x1 + a2;
    float m2 = bsum256(v2, s8, lane, wid) * (1.0f / (float)DMq);
    float c2 = v2 - m2;
    float var2 = bsum256(c2 * c2, s8, lane, wid) * (1.0f / (float)DMq);
    float xo = c2 * rsqrtf(var2 + 1e-5f) * g2[d] + b2[d];
    g_x[off] = xo;
    __nv_bfloat16 h = __float2bfloat16(xo);
    g_ahi[off] = h;
    g_alo[off] = __float2bfloat16(xo - __bfloat162float(h));
}

// ---------------- batchnorm stats (256 chunks of 32 rows) ----------------------
__global__ void bn_part_kernel() {
    int chunk = blockIdx.x;
    int d = threadIdx.x;
    float s = 0.f, s2 = 0.f;
    int r0 = chunk * 32;
    for (int r = 0; r < 32; r++) {
        float v = g_tmp[(size_t)(r0 + r) * DMq + d];
        s += v; s2 += v * v;
    }
    g_bnp1[chunk * DMq + d] = s;
    g_bnp2[chunk * DMq + d] = s2;
}

__global__ void bn_final_kernel() {
    int d = threadIdx.x;
    float s = 0.f, s2 = 0.f;
    for (int c = 0; c < 256; c++) {
        s  += g_bnp1[c * DMq + d];
        s2 += g_bnp2[c * DMq + d];
    }
    float m = s * (1.0f / (float)BLq);
    g_bnm[d] = m;
    g_bnv[d] = s2 * (1.0f / (float)BLq) - m * m;
}

__global__ void bn_elu_kernel(const float* __restrict__ gam,
                              const float* __restrict__ bet) {
    int t = blockIdx.x * blockDim.x + threadIdx.x;
    if (t >= BLq * DMq) return;
    int d = t % DMq;
    float y = (g_tmp[t] - g_bnm[d]) * rsqrtf(g_bnv[d] + 1e-5f) * gam[d] + bet[d];
    float xo = (y > 0.f) ? y : expm1f(y);
    g_x[t] = xo;
    __nv_bfloat16 h = __float2bfloat16(xo);
    g_ahi[t] = h;
    g_alo[t] = __float2bfloat16(xo - __bfloat162float(h));
}

// ---------------- final LayerNorm into d_out -----------------------------------
__global__ __launch_bounds__(256)
void final_ln_kernel(const float* __restrict__ gam,
                     const float* __restrict__ bet,
                     float* __restrict__ out) {
    __shared__ float s8[8];
    int row = blockIdx.x;
    int d = threadIdx.x;
    int lane = d & 31, wid = d >> 5;
    size_t off = (size_t)row * DMq + d;
    float v = g_x[off];
    float m = bsum256(v, s8, lane, wid) * (1.0f / (float)DMq);
    float c = v - m;
    float var = bsum256(c * c, s8, lane, wid) * (1.0f / (float)DMq);
    out[off] = c * rsqrtf(var + 1e-5f) * gam[d] + bet[d];
}

// ---------------- host driver --------------------------------------------------
extern "C" void kernel_launch(void* const* d_in, const int* in_sizes, int n_in,
                              void* d_out, int out_size) {
    const float* x_in = (const float*)d_in[0];
    const float* wq   = (const float*)d_in[1];
    const float* bq   = (const float*)d_in[2];
    const float* wk   = (const float*)d_in[3];
    const float* bk   = (const float*)d_in[4];
    const float* wv   = (const float*)d_in[5];
    const float* bv   = (const float*)d_in[6];
    const float* wo   = (const float*)d_in[7];
    const float* bo   = (const float*)d_in[8];
    const float* c1w  = (const float*)d_in[9];
    const float* c1b  = (const float*)d_in[10];
    const float* c2w  = (const float*)d_in[11];
    const float* c2b  = (const float*)d_in[12];
    const float* ln1g = (const float*)d_in[13];
    const float* ln1b = (const float*)d_in[14];
    const float* ln2g = (const float*)d_in[15];
    const float* ln2b = (const float*)d_in[16];
    const float* dcw  = (const float*)d_in[17];
    const float* dcb  = (const float*)d_in[18];
    const float* bng  = (const float*)d_in[19];
    const float* bnb  = (const float*)d_in[20];
    const float* fng  = (const float*)d_in[21];
    const float* fnb  = (const float*)d_in[22];
    float* out = (float*)d_out;

    // Real device addresses (host-shadow/ATS trap on GB300)
    void *vp;
    cudaGetSymbolAddress(&vp, g_q);   float* pq   = (float*)vp;
    cudaGetSymbolAddress(&vp, g_k);   float* pk   = (float*)vp;
    cudaGetSymbolAddress(&vp, g_v);   float* pv   = (float*)vp;

    copy_x_kernel<<<(BLq * DMq) / 256, 256>>>(x_in);

    int nw = NLq * DMq * DMq;
    split_w_kernel<<<(nw + 255) / 256, 256>>>(wq, 0);
    split_w_kernel<<<(nw + 255) / 256, 256>>>(wk, 1);
    split_w_kernel<<<(nw + 255) / 256, 256>>>(wv, 2);
    int ncw = (NLq - 1) * 3 * DMq * DMq;
    split_cw_kernel<<<(ncw + 255) / 256, 256>>>(dcw);
    rng_idx_all_kernel<<<(NLq * Lq * Uq + 255) / 256, 256>>>();

    dim3 qkvgrid(DMq / 128, BLq / 128, 3);   // (2, 64, 3)
    dim3 cgrid(DMq / 128, BLq / 128);        // (2, 64)

    for (int lay = 0; lay < NLq; lay++) {
        gemm_qkv_kernel<<<qkvgrid, 256>>>(lay,
            bq + (size_t)lay * DMq, bk + (size_t)lay * DMq, bv + (size_t)lay * DMq,
            pq, pk, pv);

        compute_M_kernel<<<(Bq * Hq * Lq * 4) / 256, 256>>>(lay);
        topk_kernel<<<Bq * Hq, 512>>>();
        vmean_part_kernel<<<dim3(32, Bq), DMq>>>();
        vmean_final_kernel<<<Bq, DMq>>>();

        const float* WO = wo + (size_t)lay * DMq * DMq;
        wo_prep_kernel<<<293, 256>>>(lay, WO, bo + (size_t)lay * DMq);
        attn_kernel<<<Bq * Hq * GRPS, 256>>>();

        post_kernel<<<BLq, DMq>>>(lay,
                                  c1w + (size_t)lay * INTERq * DMq,
                                  c1b + (size_t)lay * INTERq,
                                  c2w + (size_t)lay * DMq * INTERq,
                                  c2b + (size_t)lay * DMq,
                                  ln1g + (size_t)lay * DMq,
                                  ln1b + (size_t)lay * DMq,
                                  ln2g + (size_t)lay * DMq,
                                  ln2b + (size_t)lay * DMq);

        if (lay < NLq - 1) {
            convgemm_bf16_kernel<<<cgrid, 256>>>(lay, dcb + (size_t)lay * DMq);
            bn_part_kernel<<<256, DMq>>>();
            bn_final_kernel<<<1, DMq>>>();
            bn_elu_kernel<<<(BLq * DMq) / 256, 256>>>(
                bng + (size_t)lay * DMq,
                bnb + (size_t)lay * DMq);
        }
    }

    final_ln_kernel<<<BLq, DMq>>>(fng, fnb, out);
}

// round 15
// speedup vs baseline: 1.0340x; 1.0340x over previous
#include <cuda_runtime.h>
#include <cuda_bf16.h>
#include <math.h>
#include <stdint.h>

// Problem constants
#define Bq   4
#define Lq   2048
#define DMq  256
#define Hq   8
#define Eq   32
#define NLq  3
#define INTERq 16
#define Uq   40
#define BLq  (Bq*Lq)     // 8192
#define QB   5           // queries per attn block (40 = 8 groups * 5)
#define GRPS 8

// ---------------- scratch (device globals; no allocation allowed) -------------
__device__ float g_x[BLq*DMq];
__device__ float g_q[BLq*DMq];
__device__ float g_k[BLq*DMq];
__device__ float g_v[BLq*DMq];
__device__ float g_tmp[BLq*DMq];
__device__ __nv_bfloat16 g_ahi[BLq*DMq];
__device__ __nv_bfloat16 g_alo[BLq*DMq];
__device__ __nv_bfloat16 g_whi[12*DMq*DMq];   // [lay*4+slot][n][k]
__device__ __nv_bfloat16 g_wlo[12*DMq*DMq];
__device__ __nv_bfloat16 g_cwhi[6*DMq*DMq];   // [lay*3+t][o][i]
__device__ __nv_bfloat16 g_cwlo[6*DMq*DMq];
__device__ float g_wot[DMq*DMq];              // WO^T for current layer
__device__ float g_ybase[Bq*DMq];             // vmean @ WO^T + bo
__device__ int   g_selmap[Bq*Hq*Lq];          // tag<<12 | u, tag = lay+1
__device__ int   g_idx[NLq*Lq*Uq];
__device__ float g_M[Bq*Hq*Lq];
__device__ int   g_top[Bq*Hq*Uq];
__device__ float g_vmean[Bq*DMq];
__device__ float g_vpart[Bq*32*DMq];
__device__ float g_upd[Bq*Hq*Uq*Eq];
__device__ float g_bnp1[256*DMq];
__device__ float g_bnp2[256*DMq];
__device__ float g_bnm[DMq];
__device__ float g_bnv[DMq];

// ---------------- Threefry-2x32 (matches JAX) ---------------------------------
__host__ __device__ inline void tf2x32(uint32_t k0, uint32_t k1,
                                       uint32_t x0, uint32_t x1,
                                       uint32_t& o0, uint32_t& o1) {
    uint32_t ks[3];
    ks[0] = k0; ks[1] = k1; ks[2] = k0 ^ k1 ^ 0x1BD11BDAu;
    x0 += ks[0]; x1 += ks[1];
    const int R0[4] = {13, 15, 26, 6};
    const int R1[4] = {17, 29, 16, 24};
    #pragma unroll
    for (int i = 0; i < 5; i++) {
        #pragma unroll
        for (int j = 0; j < 4; j++) {
            int r = (i & 1) ? R1[j] : R0[j];
            x0 += x1;
            x1 = (x1 << r) | (x1 >> (32 - r));
            x1 ^= x0;
        }
        x0 += ks[(i + 1) % 3];
        x1 += ks[(i + 2) % 3] + (uint32_t)(i + 1);
    }
    o0 = x0; o1 = x1;
}

// all-layer RNG: idx[lay][f] = lower_bits(tf(split(fold_in(key42,lay))[1],(0,f))) & 2047
__global__ void rng_idx_all_kernel() {
    int t = blockIdx.x * blockDim.x + threadIdx.x;
    if (t < NLq * Lq * Uq) {
        int lay = t / (Lq * Uq);
        int f = t - lay * (Lq * Uq);
        uint32_t k0, k1, s0, s1, o0, o1;
        tf2x32(0u, 42u, 0u, (uint32_t)lay, k0, k1);
        tf2x32(k0, k1, 0u, 1u, s0, s1);
        tf2x32(s0, s1, 0u, (uint32_t)f, o0, o1);
        g_idx[t] = (int)((o0 ^ o1) & 2047u);
    }
}

// ---------------- block-sum helper (256 threads) -------------------------------
__device__ __forceinline__ float bsum256(float v, float* s8, int lane, int wid) {
    #pragma unroll
    for (int o = 16; o > 0; o >>= 1) v += __shfl_xor_sync(0xffffffffu, v, o);
    if (lane == 0) s8[wid] = v;
    __syncthreads();
    float r = s8[0] + s8[1] + s8[2] + s8[3] + s8[4] + s8[5] + s8[6] + s8[7];
    __syncthreads();
    return r;
}

// ---------------- copy input x + bf16 split ------------------------------------
__global__ void copy_x_kernel(const float* __restrict__ src) {
    int t = blockIdx.x * blockDim.x + threadIdx.x;
    if (t < BLq * DMq) {
        float v = src[t];
        g_x[t] = v;
        __nv_bfloat16 h = __float2bfloat16(v);
        g_ahi[t] = h;
        g_alo[t] = __float2bfloat16(v - __bfloat162float(h));
    }
}

__global__ void split_w_kernel(const float* __restrict__ src, int slot) {
    int t = blockIdx.x * blockDim.x + threadIdx.x;
    if (t < NLq * DMq * DMq) {
        int lay = t >> 16;
        int r = t & 65535;
        float v = src[t];
        __nv_bfloat16 h = __float2bfloat16(v);
        int d = (((lay << 2) + slot) << 16) | r;
        g_whi[d] = h;
        g_wlo[d] = __float2bfloat16(v - __bfloat162float(h));
    }
}

__global__ void split_cw_kernel(const float* __restrict__ dcw) {
    int t = blockIdx.x * blockDim.x + threadIdx.x;
    if (t < (NLq - 1) * 3 * DMq * DMq) {
        int lay = t / (3 * 65536);
        int rem = t % (3 * 65536);
        int tap = rem >> 16;
        int oi = rem & 65535;
        int o = oi >> 8;
        int i = oi & 255;
        float v = dcw[(size_t)lay * 3 * 65536 + o * 768 + i * 3 + tap];
        __nv_bfloat16 h = __float2bfloat16(v);
        g_cwhi[t] = h;
        g_cwlo[t] = __float2bfloat16(v - __bfloat162float(h));
    }
}

// ---------------- split-bf16 tensor-core GEMM ----------------------------------
#define MMA_BF16(c, a, b) \
    asm volatile("mma.sync.aligned.m16n8k16.row.col.f32.bf16.bf16.f32 " \
        "{%0,%1,%2,%3}, {%4,%5,%6,%7}, {%8,%9}, {%0,%1,%2,%3};" \
        : "+f"((c)[0]), "+f"((c)[1]), "+f"((c)[2]), "+f"((c)[3]) \
        : "r"((a)[0]), "r"((a)[1]), "r"((a)[2]), "r"((a)[3]), \
          "r"((b)[0]), "r"((b)[1]))

// fused QKV: grid (2, 64, 3), 256 threads
__global__ __launch_bounds__(256)
void gemm_qkv_kernel(int lay,
                     const float* __restrict__ bq,
                     const float* __restrict__ bk,
                     const float* __restrict__ bv,
                     float* __restrict__ Cq,
                     float* __restrict__ Ck,
                     float* __restrict__ Cv) {
    __shared__ __nv_bfloat16 sAh[2][128*24], sAl[2][128*24];
    __shared__ __nv_bfloat16 sBh[2][128*24], sBl[2][128*24];
    int z = blockIdx.z;
    int slot = lay * 4 + z;
    const float* bias = (z == 0) ? bq : (z == 1) ? bk : bv;
    float* C = (z == 0) ? Cq : (z == 1) ? Ck : Cv;

    int tid = threadIdx.x;
    int m0 = blockIdx.y * 128, n0 = blockIdx.x * 128;
    int lr = tid >> 1, lh = tid & 1;
    int w = tid >> 5, lane = tid & 31;
    int wm = w & 1, wn = w >> 1;
    int grp = lane >> 2, tig = lane & 3;

    const __nv_bfloat16* Wh = g_whi + (size_t)slot * DMq * DMq;
    const __nv_bfloat16* Wl = g_wlo + (size_t)slot * DMq * DMq;
    size_t aoff = (size_t)(m0 + lr) * DMq + lh * 8;
    size_t boff = (size_t)(n0 + lr) * DMq + lh * 8;
    int sidx = lr * 24 + lh * 8;

    float acc[4][4][4];
    #pragma unroll
    for (int i = 0; i < 4; i++)
        #pragma unroll
        for (int j = 0; j < 4; j++)
            #pragma unroll
            for (int q = 0; q < 4; q++) acc[i][j][q] = 0.f;

    uint4 rah = *(const uint4*)(g_ahi + aoff);
    uint4 ral = *(const uint4*)(g_alo + aoff);
    uint4 rbh = *(const uint4*)(Wh + boff);
    uint4 rbl = *(const uint4*)(Wl + boff);

    for (int c = 0; c < 16; c++) {
        int p = c & 1;
        *(uint4*)(sAh[p] + sidx) = rah;
        *(uint4*)(sAl[p] + sidx) = ral;
        *(uint4*)(sBh[p] + sidx) = rbh;
        *(uint4*)(sBl[p] + sidx) = rbl;
        __syncthreads();
        if (c + 1 < 16) {
            rah = *(const uint4*)(g_ahi + aoff + (c + 1) * 16);
            ral = *(const uint4*)(g_alo + aoff + (c + 1) * 16);
            rbh = *(const uint4*)(Wh + boff + (c + 1) * 16);
            rbl = *(const uint4*)(Wl + boff + (c + 1) * 16);
        }
        uint32_t bh[4][2], bl[4][2];
        #pragma unroll
        for (int nf = 0; nf < 4; nf++) {
            int n = wn * 32 + nf * 8 + grp;
            bh[nf][0] = *(const uint32_t*)(sBh[p] + n * 24 + tig * 2);
            bh[nf][1] = *(const uint32_t*)(sBh[p] + n * 24 + tig * 2 + 8);
            bl[nf][0] = *(const uint32_t*)(sBl[p] + n * 24 + tig * 2);
            bl[nf][1] = *(const uint32_t*)(sBl[p] + n * 24 + tig * 2 + 8);
        }
        #pragma unroll
        for (int mf = 0; mf < 4; mf++) {
            int r = wm * 64 + mf * 16 + grp;
            uint32_t ah[4], al[4];
            ah[0] = *(const uint32_t*)(sAh[p] + r * 24 + tig * 2);
            ah[1] = *(const uint32_t*)(sAh[p] + (r + 8) * 24 + tig * 2);
            ah[2] = *(const uint32_t*)(sAh[p] + r * 24 + tig * 2 + 8);
            ah[3] = *(const uint32_t*)(sAh[p] + (r + 8) * 24 + tig * 2 + 8);
            al[0] = *(const uint32_t*)(sAl[p] + r * 24 + tig * 2);
            al[1] = *(const uint32_t*)(sAl[p] + (r + 8) * 24 + tig * 2);
            al[2] = *(const uint32_t*)(sAl[p] + r * 24 + tig * 2 + 8);
            al[3] = *(const uint32_t*)(sAl[p] + (r + 8) * 24 + tig * 2 + 8);
            #pragma unroll
            for (int nf = 0; nf < 4; nf++) {
                MMA_BF16(acc[mf][nf], ah, bh[nf]);
                MMA_BF16(acc[mf][nf], ah, bl[nf]);
                MMA_BF16(acc[mf][nf], al, bh[nf]);
            }
        }
    }

    #pragma unroll
    for (int mf = 0; mf < 4; mf++) {
        int r0 = m0 + wm * 64 + mf * 16 + grp;
        #pragma unroll
        for (int nf = 0; nf < 4; nf++) {
            int c0 = n0 + wn * 32 + nf * 8 + tig * 2;
            float2 v0 = {acc[mf][nf][0] + bias[c0], acc[mf][nf][1] + bias[c0 + 1]};
            float2 v1 = {acc[mf][nf][2] + bias[c0], acc[mf][nf][3] + bias[c0 + 1]};
            *(float2*)&C[(size_t)r0 * DMq + c0] = v0;
            *(float2*)&C[(size_t)(r0 + 8) * DMq + c0] = v1;
        }
    }
}

// ---------------- conv as 3-tap split-bf16 GEMM --------------------------------
__global__ __launch_bounds__(256)
void convgemm_bf16_kernel(int lay, const float* __restrict__ cb) {
    __shared__ __nv_bfloat16 sAh[2][128*24], sAl[2][128*24];
    __shared__ __nv_bfloat16 sBh[2][128*24], sBl[2][128*24];
    int tid = threadIdx.x;
    int m0 = blockIdx.y * 128, n0 = blockIdx.x * 128;
    int lr = tid >> 1, lh = tid & 1;
    int w = tid >> 5, lane = tid & 31;
    int wm = w & 1, wn = w >> 1;
    int grp = lane >> 2, tig = lane & 3;

    int m = m0 + lr;
    int b = m >> 11;
    int l = m & 2047;
    size_t aoff[3];
    #pragma unroll
    for (int t = 0; t < 3; t++)
        aoff[t] = (size_t)((b << 11) | ((l + t + 2047) & 2047)) * DMq + lh * 8;
    const __nv_bfloat16* Wh3 = g_cwhi + (size_t)(lay * 3) * DMq * DMq;
    const __nv_bfloat16* Wl3 = g_cwlo + (size_t)(lay * 3) * DMq * DMq;
    size_t boff = (size_t)(n0 + lr) * DMq + lh * 8;
    int sidx = lr * 24 + lh * 8;

    float acc[4][4][4];
    #pragma unroll
    for (int i = 0; i < 4; i++)
        #pragma unroll
        for (int j = 0; j < 4; j++)
            #pragma unroll
            for (int q = 0; q < 4; q++) acc[i][j][q] = 0.f;

    uint4 rah = *(const uint4*)(g_ahi + aoff[0]);
    uint4 ral = *(const uint4*)(g_alo + aoff[0]);
    uint4 rbh = *(const uint4*)(Wh3 + boff);
    uint4 rbl = *(const uint4*)(Wl3 + boff);

    for (int kt = 0; kt < 48; kt++) {
        int p = kt & 1;
        *(uint4*)(sAh[p] + sidx) = rah;
        *(uint4*)(sAl[p] + sidx) = ral;
        *(uint4*)(sBh[p] + sidx) = rbh;
        *(uint4*)(sBl[p] + sidx) = rbl;
        __syncthreads();
        if (kt + 1 < 48) {
            int t2 = (kt + 1) >> 4;
            int c2 = ((kt + 1) & 15) * 16;
            rah = *(const uint4*)(g_ahi + aoff[t2] + c2);
            ral = *(const uint4*)(g_alo + aoff[t2] + c2);
            rbh = *(const uint4*)(Wh3 + (size_t)t2 * DMq * DMq + boff + c2);
            rbl = *(const uint4*)(Wl3 + (size_t)t2 * DMq * DMq + boff + c2);
        }
        uint32_t bh[4][2], bl[4][2];
        #pragma unroll
        for (int nf = 0; nf < 4; nf++) {
            int n = wn * 32 + nf * 8 + grp;
            bh[nf][0] = *(const uint32_t*)(sBh[p] + n * 24 + tig * 2);
            bh[nf][1] = *(const uint32_t*)(sBh[p] + n * 24 + tig * 2 + 8);
            bl[nf][0] = *(const uint32_t*)(sBl[p] + n * 24 + tig * 2);
            bl[nf][1] = *(const uint32_t*)(sBl[p] + n * 24 + tig * 2 + 8);
        }
        #pragma unroll
        for (int mf = 0; mf < 4; mf++) {
            int r = wm * 64 + mf * 16 + grp;
            uint32_t ah[4], al[4];
            ah[0] = *(const uint32_t*)(sAh[p] + r * 24 + tig * 2);
            ah[1] = *(const uint32_t*)(sAh[p] + (r + 8) * 24 + tig * 2);
            ah[2] = *(const uint32_t*)(sAh[p] + r * 24 + tig * 2 + 8);
            ah[3] = *(const uint32_t*)(sAh[p] + (r + 8) * 24 + tig * 2 + 8);
            al[0] = *(const uint32_t*)(sAl[p] + r * 24 + tig * 2);
            al[1] = *(const uint32_t*)(sAl[p] + (r + 8) * 24 + tig * 2);
            al[2] = *(const uint32_t*)(sAl[p] + r * 24 + tig * 2 + 8);
            al[3] = *(const uint32_t*)(sAl[p] + (r + 8) * 24 + tig * 2 + 8);
            #pragma unroll
            for (int nf = 0; nf < 4; nf++) {
                MMA_BF16(acc[mf][nf], ah, bh[nf]);
                MMA_BF16(acc[mf][nf], ah, bl[nf]);
                MMA_BF16(acc[mf][nf], al, bh[nf]);
            }
        }
    }

    #pragma unroll
    for (int mf = 0; mf < 4; mf++) {
        int r0 = m0 + wm * 64 + mf * 16 + grp;
        #pragma unroll
        for (int nf = 0; nf < 4; nf++) {
            int c0 = n0 + wn * 32 + nf * 8 + tig * 2;
            float2 v0 = {acc[mf][nf][0] + cb[c0], acc[mf][nf][1] + cb[c0 + 1]};
            float2 v1 = {acc[mf][nf][2] + cb[c0], acc[mf][nf][3] + cb[c0 + 1]};
            *(float2*)&g_tmp[(size_t)r0 * DMq + c0] = v0;
            *(float2*)&g_tmp[(size_t)(r0 + 8) * DMq + c0] = v1;
        }
    }
}

// ---------------- M: 4 threads per query ---------------------------------------
__global__ void compute_M_kernel(int lay) {
    int t = blockIdx.x * blockDim.x + threadIdx.x;
    int q = t >> 2;
    int j = t & 3;
    int l = q & (Lq - 1);
    int bh = q >> 11;
    int h = bh & (Hq - 1);
    int b = bh >> 3;
    const int* idx = g_idx + lay * (Lq * Uq);
    const float4* qp = (const float4*)(g_q + ((size_t)(b * Lq + l) * DMq + h * Eq + j * 8));
    float4 q0 = qp[0], q1 = qp[1];
    float mx = -INFINITY, sm = 0.f;
    #pragma unroll 4
    for (int s = 0; s < Uq; s++) {
        int kl = idx[l * Uq + s];
        const float4* kp = (const float4*)(g_k + ((size_t)(b * Lq + kl) * DMq + h * Eq + j * 8));
        float4 k0 = kp[0], k1 = kp[1];
        float d = q0.x*k0.x + q0.y*k0.y + q0.z*k0.z + q0.w*k0.w
                + q1.x*k1.x + q1.y*k1.y + q1.z*k1.z + q1.w*k1.w;
        d += __shfl_xor_sync(0xffffffffu, d, 1);
        d += __shfl_xor_sync(0xffffffffu, d, 2);
        mx = fmaxf(mx, d);
        sm += d;
    }
    if (j == 0) g_M[q] = mx - sm * (1.0f / (float)Lq);
}

// ---------------- top-k via full bitonic sort ----------------------------------
__device__ inline uint32_t fsortable(float f) {
    uint32_t u = __float_as_uint(f);
    return (u & 0x80000000u) ? ~u : (u | 0x80000000u);
}

__global__ __launch_bounds__(512)
void topk_kernel() {
    __shared__ unsigned long long key[Lq];
    int bh = blockIdx.x;
    int tid = threadIdx.x;
    const float* Mrow = g_M + (size_t)bh * Lq;
    for (int i = tid; i < Lq; i += 512) {
        uint32_t s = fsortable(Mrow[i]);
        key[i] = ((unsigned long long)(~s) << 32) | (uint32_t)i;
    }
    for (int k = 2; k <= Lq; k <<= 1) {
        for (int j = k >> 1; j > 0; j >>= 1) {
            __syncthreads();
            for (int i = tid; i < Lq; i += 512) {
                int l = i ^ j;
                if (l > i) {
                    unsigned long long a = key[i], c = key[l];
                    bool asc = ((i & k) == 0);
                    if ((a > c) == asc) { key[i] = c; key[l] = a; }
                }
            }
        }
    }
    __syncthreads();
    if (tid < Uq) g_top[bh * Uq + tid] = (int)(key[tid] & 0xffffffffu);
}

// ---------------- mean of v over L: two-stage ----------------------------------
__global__ void vmean_part_kernel() {
    int b = blockIdx.y;
    int chunk = blockIdx.x;
    int d = threadIdx.x;
    float s = 0.f;
    int r0 = chunk * 64;
    for (int r = 0; r < 64; r++)
        s += g_v[(size_t)(b * Lq + r0 + r) * DMq + d];
    g_vpart[(size_t)(b * 32 + chunk) * DMq + d] = s;
}

__global__ void vmean_final_kernel() {
    int b = blockIdx.x;
    int d = threadIdx.x;
    float s = 0.f;
    for (int c = 0; c < 32; c++) s += g_vpart[(size_t)(b * 32 + c) * DMq + d];
    g_vmean[b * DMq + d] = s * (1.0f / (float)Lq);
}

// ---------------- attention: QB=5 queries per block, 8 groups ------------------
__global__ __launch_bounds__(256)
void attn_kernel() {
    __shared__ float sp[QB][Lq];           // 40KB
    __shared__ float qs[QB][Eq];
    __shared__ float redm[QB][8];
    __shared__ float reds[QB][8];
    __shared__ float outacc[8][QB][Eq];    // 5KB
    const float SCALE = 0.17677669529663687f;
    int blk = blockIdx.x;
    int grp = blk % GRPS;
    int bh = blk / GRPS;
    int h = bh & (Hq - 1);
    int b = bh >> 3;
    int tid = threadIdx.x;
    int lane = tid & 31;
    int wid = tid >> 5;

    for (int i = tid; i < QB * Eq; i += 256) {
        int qq = i >> 5, e = i & 31;
        int lqi = g_top[bh * Uq + grp * QB + qq];
        qs[qq][e] = g_q[(size_t)(b * Lq + lqi) * DMq + h * Eq + e];
    }
    __syncthreads();

    float lmax[QB];
    #pragma unroll
    for (int qq = 0; qq < QB; qq++) lmax[qq] = -INFINITY;
    for (int kk = tid; kk < Lq; kk += 256) {
        const float4* k4 = (const float4*)(g_k + ((size_t)(b * Lq + kk) * DMq + h * Eq));
        float4 kv[8];
        #pragma unroll
        for (int j = 0; j < 8; j++) kv[j] = k4[j];
        #pragma unroll
        for (int qq = 0; qq < QB; qq++) {
            const float4* q4 = (const float4*)qs[qq];
            float d = 0.f;
            #pragma unroll
            for (int j = 0; j < 8; j++) {
                float4 qv = q4[j];
                d += qv.x*kv[j].x + qv.y*kv[j].y + qv.z*kv[j].z + qv.w*kv[j].w;
            }
            d *= SCALE;
            sp[qq][kk] = d;
            lmax[qq] = fmaxf(lmax[qq], d);
        }
    }
    #pragma unroll
    for (int qq = 0; qq < QB; qq++) {
        float v = lmax[qq];
        #pragma unroll
        for (int off = 16; off > 0; off >>= 1)
            v = fmaxf(v, __shfl_xor_sync(0xffffffffu, v, off));
        if (lane == 0) redm[qq][wid] = v;
    }
    __syncthreads();
    float gmax[QB];
    #pragma unroll
    for (int qq = 0; qq < QB; qq++) {
        float v = redm[qq][0];
        #pragma unroll
        for (int w2 = 1; w2 < 8; w2++) v = fmaxf(v, redm[qq][w2]);
        gmax[qq] = v;
    }

    float lsum[QB];
    #pragma unroll
    for (int qq = 0; qq < QB; qq++) lsum[qq] = 0.f;
    for (int kk = tid; kk < Lq; kk += 256) {
        #pragma unroll
        for (int qq = 0; qq < QB; qq++) {
            float p = expf(sp[qq][kk] - gmax[qq]);
            sp[qq][kk] = p;
            lsum[qq] += p;
        }
    }
    #pragma unroll
    for (int qq = 0; qq < QB; qq++) {
        float v = lsum[qq];
        #pragma unroll
        for (int off = 16; off > 0; off >>= 1)
            v += __shfl_xor_sync(0xffffffffu, v, off);
        if (lane == 0) reds[qq][wid] = v;
    }
    __syncthreads();
    float ginv[QB];
    #pragma unroll
    for (int qq = 0; qq < QB; qq++) {
        float v = 0.f;
        #pragma unroll
        for (int w2 = 0; w2 < 8; w2++) v += reds[qq][w2];
        ginv[qq] = 1.0f / v;
    }

    {
        int e = lane;
        float acc[QB];
        #pragma unroll
        for (int qq = 0; qq < QB; qq++) acc[qq] = 0.f;
        for (int kk = wid; kk < Lq; kk += 8) {
            float vv = g_v[(size_t)(b * Lq + kk) * DMq + h * Eq + e];
            #pragma unroll
            for (int qq = 0; qq < QB; qq++)
                acc[qq] += sp[qq][kk] * vv;
        }
        #pragma unroll
        for (int qq = 0; qq < QB; qq++) outacc[wid][qq][e] = acc[qq];
    }
    __syncthreads();
    if (tid < QB * Eq) {
        int qq = tid >> 5, e = tid & 31;
        float s = 0.f;
        #pragma unroll
        for (int w2 = 0; w2 < 8; w2++) s += outacc[w2][qq][e];
        g_upd[((size_t)bh * Uq + grp * QB + qq) * Eq + e] = s * ginv[qq];
    }
}

// ---------------- WO prep: wot transpose + ybase + selmap set ------------------
__global__ __launch_bounds__(256)
void wo_prep_kernel(int lay, const float* __restrict__ WO,
                    const float* __restrict__ bo) {
    int bid = blockIdx.x;
    int tid = threadIdx.x;
    if (bid < 256) {
        int t = bid * 256 + tid;           // t = d*256+n
        int d = t >> 8, n = t & 255;
        g_wot[t] = WO[n * DMq + d];
    } else if (bid < 288) {
        __shared__ float vm[DMq];
        int q = bid - 256;
        int b = q >> 3, ng = q & 7;
        vm[tid] = g_vmean[b * DMq + tid];
        __syncthreads();
        int nl = tid >> 3, dc = tid & 7;
        int n = ng * 32 + nl;
        const float4* w4 = (const float4*)(WO + (size_t)n * DMq + dc * 32);
        float s = 0.f;
        #pragma unroll
        for (int i = 0; i < 8; i++) {
            float4 wv = w4[i];
            int d0 = dc * 32 + i * 4;
            s += vm[d0]*wv.x + vm[d0+1]*wv.y + vm[d0+2]*wv.z + vm[d0+3]*wv.w;
        }
        s += __shfl_down_sync(0xffffffffu, s, 4);
        s += __shfl_down_sync(0xffffffffu, s, 2);
        s += __shfl_down_sync(0xffffffffu, s, 1);
        if (dc == 0) g_ybase[b * DMq + n] = s + bo[n];
    } else {
        int t = (bid - 288) * 256 + tid;   // B*H*U = 1280
        if (t < Bq * Hq * Uq) {
            int u = t % Uq;
            int bh = t / Uq;
            int l = g_top[t];
            g_selmap[bh * Lq + l] = ((lay + 1) << 12) | u;
        }
    }
}

// ---------------- fused: WO-apply -> LN1 -> FFN -> +res -> LN2 -> split --------
__global__ __launch_bounds__(256)
void post_kernel(int lay,
                 const float* __restrict__ c1w,
                 const float* __restrict__ c1b,
                 const float* __restrict__ c2w,
                 const float* __restrict__ c2b,
                 const float* __restrict__ g1,
                 const float* __restrict__ b1,
                 const float* __restrict__ g2,
                 const float* __restrict__ b2) {
    __shared__ float s8[8];
    __shared__ float xs[DMq];
    __shared__ float ys[INTERq];
    __shared__ int su[8];
    __shared__ float sdelta[8][Eq];
    int row = blockIdx.x;            // b*2048 + l
    int b = row >> 11;
    int l = row & 2047;
    int d = threadIdx.x;
    int lane = d & 31, wid = d >> 5;
    size_t off = (size_t)row * DMq + d;

    // --- inline wo_apply: acc = attention-output row @ WO^T + bo ---
    int tag = (lay + 1) << 12;
    if (d < 8) {
        int vv = g_selmap[(b * 8 + d) * Lq + l];
        su[d] = ((vv & ~4095) == tag) ? (vv & 4095) : -1;
    }
    __syncthreads();
    bool any = su[0] >= 0 || su[1] >= 0 || su[2] >= 0 || su[3] >= 0 ||
               su[4] >= 0 || su[5] >= 0 || su[6] >= 0 || su[7] >= 0;
    float acc = g_ybase[b * DMq + d];
    if (any) {
        int h = d >> 5, e = d & 31;
        int u = su[h];
        sdelta[h][e] = (u >= 0)
            ? g_upd[(((size_t)(b * 8 + h)) * Uq + u) * Eq + e] - g_vmean[b * DMq + h * 32 + e]
            : 0.f;
        __syncthreads();
        #pragma unroll
        for (int h2 = 0; h2 < 8; h2++) {
            if (su[h2] >= 0) {
                #pragma unroll
                for (int e2 = 0; e2 < 32; e2++)
                    acc += sdelta[h2][e2] * g_wot[(h2 * 32 + e2) * DMq + d];
            }
        }
    }

    // --- LN1(x + acc) ---
    float v = g_x[off] + acc;
    float m = bsum256(v, s8, lane, wid) * (1.0f / (float)DMq);
    float c = v - m;
    float var = bsum256(c * c, s8, lane, wid) * (1.0f / (float)DMq);
    float x1 = c * rsqrtf(var + 1e-5f) * g1[d] + b1[d];
    xs[d] = x1;
    __syncthreads();
    int f = d >> 4, kc = d & 15;
    const float4* w4 = (const float4*)(c1w + (size_t)f * DMq + kc * 16);
    float p = 0.f;
    #pragma unroll
    for (int i = 0; i < 4; i++) {
        float4 wv = w4[i];
        int k0 = kc * 16 + i * 4;
        p += xs[k0]*wv.x + xs[k0+1]*wv.y + xs[k0+2]*wv.z + xs[k0+3]*wv.w;
    }
    p += __shfl_down_sync(0xffffffffu, p, 8);
    p += __shfl_down_sync(0xffffffffu, p, 4);
    p += __shfl_down_sync(0xffffffffu, p, 2);
    p += __shfl_down_sync(0xffffffffu, p, 1);
    if (kc == 0) ys[f] = fmaxf(p + c1b[f], 0.f);
    __syncthreads();
    float a2 = c2b[d];
    const float* w2 = c2w + (size_t)d * INTERq;
    #pragma unroll
    for (int ff = 0; ff < INTERq; ff++) a2 += ys[ff] * w2[ff];
    float v2 = x1 + a2;
    float m2 = bsum256(v2, s8, lane, wid) * (1.0f / (float)DMq);
    float c2 = v2 - m2;
    float var2 = bsum256(c2 * c2, s8, lane, wid) * (1.0f / (float)DMq);
    float xo = c2 * rsqrtf(var2 + 1e-5f) * g2[d] + b2[d];
    g_x[off] = xo;
    __nv_bfloat16 h = __float2bfloat16(xo);
    g_ahi[off] = h;
    g_alo[off] = __float2bfloat16(xo - __bfloat162float(h));
}

// ---------------- batchnorm stats (256 chunks of 32 rows) ----------------------
__global__ void bn_part_kernel() {
    int chunk = blockIdx.x;
    int d = threadIdx.x;
    float s = 0.f, s2 = 0.f;
    int r0 = chunk * 32;
    for (int r = 0; r < 32; r++) {
        float v = g_tmp[(size_t)(r0 + r) * DMq + d];
        s += v; s2 += v * v;
    }
    g_bnp1[chunk * DMq + d] = s;
    g_bnp2[chunk * DMq + d] = s2;
}

__global__ void bn_final_kernel() {
    int d = threadIdx.x;
    float s = 0.f, s2 = 0.f;
    for (int c = 0; c < 256; c++) {
        s  += g_bnp1[c * DMq + d];
        s2 += g_bnp2[c * DMq + d];
    }
    float m = s * (1.0f / (float)BLq);
    g_bnm[d] = m;
    g_bnv[d] = s2 * (1.0f / (float)BLq) - m * m;
}

__global__ void bn_elu_kernel(const float* __restrict__ gam,
                              const float* __restrict__ bet) {
    int t = blockIdx.x * blockDim.x + threadIdx.x;
    if (t >= BLq * DMq) return;
    int d = t % DMq;
    float y = (g_tmp[t] - g_bnm[d]) * rsqrtf(g_bnv[d] + 1e-5f) * gam[d] + bet[d];
    float xo = (y > 0.f) ? y : expm1f(y);
    g_x[t] = xo;
    __nv_bfloat16 h = __float2bfloat16(xo);
    g_ahi[t] = h;
    g_alo[t] = __float2bfloat16(xo - __bfloat162float(h));
}

// ---------------- final LayerNorm into d_out -----------------------------------
__global__ __launch_bounds__(256)
void final_ln_kernel(const float* __restrict__ gam,
                     const float* __restrict__ bet,
                     float* __restrict__ out) {
    __shared__ float s8[8];
    int row = blockIdx.x;
    int d = threadIdx.x;
    int lane = d & 31, wid = d >> 5;
    size_t off = (size_t)row * DMq + d;
    float v = g_x[off];
    float m = bsum256(v, s8, lane, wid) * (1.0f / (float)DMq);
    float c = v - m;
    float var = bsum256(c * c, s8, lane, wid) * (1.0f / (float)DMq);
    out[off] = c * rsqrtf(var + 1e-5f) * gam[d] + bet[d];
}

// ---------------- host driver --------------------------------------------------
extern "C" void kernel_launch(void* const* d_in, const int* in_sizes, int n_in,
                              void* d_out, int out_size) {
    const float* x_in = (const float*)d_in[0];
    const float* wq   = (const float*)d_in[1];
    const float* bq   = (const float*)d_in[2];
    const float* wk   = (const float*)d_in[3];
    const float* bk   = (const float*)d_in[4];
    const float* wv   = (const float*)d_in[5];
    const float* bv   = (const float*)d_in[6];
    const float* wo   = (const float*)d_in[7];
    const float* bo   = (const float*)d_in[8];
    const float* c1w  = (const float*)d_in[9];
    const float* c1b  = (const float*)d_in[10];
    const float* c2w  = (const float*)d_in[11];
    const float* c2b  = (const float*)d_in[12];
    const float* ln1g = (const float*)d_in[13];
    const float* ln1b = (const float*)d_in[14];
    const float* ln2g = (const float*)d_in[15];
    const float* ln2b = (const float*)d_in[16];
    const float* dcw  = (const float*)d_in[17];
    const float* dcb  = (const float*)d_in[18];
    const float* bng  = (const float*)d_in[19];
    const float* bnb  = (const float*)d_in[20];
    const float* fng  = (const float*)d_in[21];
    const float* fnb  = (const float*)d_in[22];
    float* out = (float*)d_out;

    // Real device addresses (host-shadow/ATS trap on GB300)
    void *vp;
    cudaGetSymbolAddress(&vp, g_q);   float* pq   = (float*)vp;
    cudaGetSymbolAddress(&vp, g_k);   float* pk   = (float*)vp;
    cudaGetSymbolAddress(&vp, g_v);   float* pv   = (float*)vp;

    copy_x_kernel<<<(BLq * DMq) / 256, 256>>>(x_in);

    int nw = NLq * DMq * DMq;
    split_w_kernel<<<(nw + 255) / 256, 256>>>(wq, 0);
    split_w_kernel<<<(nw + 255) / 256, 256>>>(wk, 1);
    split_w_kernel<<<(nw + 255) / 256, 256>>>(wv, 2);
    int ncw = (NLq - 1) * 3 * DMq * DMq;
    split_cw_kernel<<<(ncw + 255) / 256, 256>>>(dcw);
    rng_idx_all_kernel<<<(NLq * Lq * Uq + 255) / 256, 256>>>();

    dim3 qkvgrid(DMq / 128, BLq / 128, 3);   // (2, 64, 3)
    dim3 cgrid(DMq / 128, BLq / 128);        // (2, 64)

    for (int lay = 0; lay < NLq; lay++) {
        gemm_qkv_kernel<<<qkvgrid, 256>>>(lay,
            bq + (size_t)lay * DMq, bk + (size_t)lay * DMq, bv + (size_t)lay * DMq,
            pq, pk, pv);

        compute_M_kernel<<<(Bq * Hq * Lq * 4) / 256, 256>>>(lay);
        topk_kernel<<<Bq * Hq, 512>>>();
        vmean_part_kernel<<<dim3(32, Bq), DMq>>>();
        vmean_final_kernel<<<Bq, DMq>>>();

        const float* WO = wo + (size_t)lay * DMq * DMq;
        wo_prep_kernel<<<293, 256>>>(lay, WO, bo + (size_t)lay * DMq);
        attn_kernel<<<Bq * Hq * GRPS, 256>>>();

        post_kernel<<<BLq, DMq>>>(lay,
                                  c1w + (size_t)lay * INTERq * DMq,
                                  c1b + (size_t)lay * INTERq,
                                  c2w + (size_t)lay * DMq * INTERq,
                                  c2b + (size_t)lay * DMq,
                                  ln1g + (size_t)lay * DMq,
                                  ln1b + (size_t)lay * DMq,
                                  ln2g + (size_t)lay * DMq,
                                  ln2b + (size_t)lay * DMq);

        if (lay < NLq - 1) {
            convgemm_bf16_kernel<<<cgrid, 256>>>(lay, dcb + (size_t)lay * DMq);
            bn_part_kernel<<<256, DMq>>>();
            bn_final_kernel<<<1, DMq>>>();
            bn_elu_kernel<<<(BLq * DMq) / 256, 256>>>(
                bng + (size_t)lay * DMq,
                bnb + (size_t)lay * DMq);
        }
    }

    final_ln_kernel<<<BLq, DMq>>>(fng, fnb, out);
}